// round 5
// baseline (speedup 1.0000x reference)
#include <cuda_runtime.h>
#include <cstdint>
#include <math.h>

#define B_    64
#define NREF  256
#define NPTS  2048
#define DIM   128
#define EPSV  0.001f
#define SCALE 1000.0f
#define LOG_WX (-5.5451748845f)   /* log(1/256 + 1e-8)  */
#define LOG_WY (-7.6245985065f)   /* log(1/2048 + 1e-8) */
#define ITERS 100
#define FULLM 0xffffffffu
#define NEG_INF __int_as_float(0xff800000)
#define TOLS  0.02f

#define RK      32      /* row candidate cap   */
#define CK      64      /* col candidate cap   */
#define MARGIN  60.0f   /* list collection margin (scaled units) */
#define ALIM    16.0f   /* max accumulated drift for sparse iters */
#define RBLIM   64.0f   /* rebuild lists only when drift below this */

// -------- device scratch (allocation-free per harness rules) --------
__device__ float g_C[(size_t)B_ * NREF * NPTS];   // 134 MB cost matrix
__device__ float g_us[B_ * NREF];
__device__ float g_vs[B_ * NPTS];
__device__ float g_x2[B_ * NPTS];
__device__ float g_r2[NREF];

// sparse candidate lists
__device__ int            g_rcnt[B_ * NREF];
__device__ unsigned short g_ridx[(size_t)B_ * NREF * RK];      // [row][k]
__device__ float          g_rval[(size_t)B_ * NREF * RK];      // [row][k]  (Cs = 1000*C)
__device__ int            g_ccnt[B_ * NPTS];
__device__ unsigned char  g_cidx[(size_t)B_ * CK * NPTS];      // [b][k][j]
__device__ float          g_cval[(size_t)B_ * CK * NPTS];      // [b][k][j]

__device__ __forceinline__ unsigned int smem_u32(const void* p) {
    unsigned int a;
    asm("{ .reg .u64 t; cvta.to.shared.u64 t, %1; cvt.u32.u64 %0, t; }" : "=r"(a) : "l"(p));
    return a;
}
__device__ __forceinline__ void st_peer_f32(unsigned int local_addr, int peer, float v) {
    unsigned int rem;
    asm volatile("mapa.shared::cluster.u32 %0, %1, %2;" : "=r"(rem) : "r"(local_addr), "r"(peer));
    asm volatile("st.shared::cluster.f32 [%0], %1;" :: "r"(rem), "f"(v) : "memory");
}
__device__ __forceinline__ void cluster_sync_() {
    asm volatile("barrier.cluster.arrive.aligned;" ::: "memory");
    asm volatile("barrier.cluster.wait.aligned;" ::: "memory");
}

// -------- squared norms --------
__global__ void aux_kernel(const float* __restrict__ X, const float* __restrict__ REF) {
    int gw   = (blockIdx.x * blockDim.x + threadIdx.x) >> 5;
    int lane = threadIdx.x & 31;
    if (gw < B_ * NPTS) {
        const float* r = X + (size_t)gw * DIM;
        float s = 0.f;
        #pragma unroll
        for (int k = lane; k < DIM; k += 32) { float t = r[k]; s = fmaf(t, t, s); }
        #pragma unroll
        for (int o = 16; o; o >>= 1) s += __shfl_xor_sync(FULLM, s, o);
        if (!lane) g_x2[gw] = s;
    } else if (gw < B_ * NPTS + NREF) {
        int i = gw - B_ * NPTS;
        const float* r = REF + i * DIM;
        float s = 0.f;
        #pragma unroll
        for (int k = lane; k < DIM; k += 32) { float t = r[k]; s = fmaf(t, t, s); }
        #pragma unroll
        for (int o = 16; o; o >>= 1) s += __shfl_xor_sync(FULLM, s, o);
        if (!lane) g_r2[i] = s;
    }
}

// -------- C[b,i,j] = sqrt(max(r2_i + x2_bj - 2*dot, 0)) --------
__global__ __launch_bounds__(256) void c_kernel(const float* __restrict__ X,
                                                const float* __restrict__ REF) {
    __shared__ float sA[32][65];
    __shared__ float sB[32][65];
    int b  = blockIdx.z;
    int i0 = blockIdx.y * 64, j0 = blockIdx.x * 64;
    int tid = threadIdx.x;
    int ti = tid >> 4, tj = tid & 15;
    const float* Xb = X + (size_t)b * NPTS * DIM;

    float acc[4][4];
    #pragma unroll
    for (int a = 0; a < 4; a++)
        #pragma unroll
        for (int c = 0; c < 4; c++) acc[a][c] = 0.f;

    for (int k0 = 0; k0 < DIM; k0 += 32) {
        #pragma unroll
        for (int r = 0; r < 8; r++) {
            int e  = r * 256 + tid;
            int ii = e >> 5, kk = e & 31;
            sA[kk][ii] = REF[(i0 + ii) * DIM + k0 + kk];
            sB[kk][ii] = Xb[(size_t)(j0 + ii) * DIM + k0 + kk];
        }
        __syncthreads();
        #pragma unroll
        for (int kk = 0; kk < 32; kk++) {
            float a0 = sA[kk][ti*4+0], a1 = sA[kk][ti*4+1], a2 = sA[kk][ti*4+2], a3 = sA[kk][ti*4+3];
            float b0 = sB[kk][tj*4+0], b1 = sB[kk][tj*4+1], b2 = sB[kk][tj*4+2], b3 = sB[kk][tj*4+3];
            acc[0][0]=fmaf(a0,b0,acc[0][0]); acc[0][1]=fmaf(a0,b1,acc[0][1]); acc[0][2]=fmaf(a0,b2,acc[0][2]); acc[0][3]=fmaf(a0,b3,acc[0][3]);
            acc[1][0]=fmaf(a1,b0,acc[1][0]); acc[1][1]=fmaf(a1,b1,acc[1][1]); acc[1][2]=fmaf(a1,b2,acc[1][2]); acc[1][3]=fmaf(a1,b3,acc[1][3]);
            acc[2][0]=fmaf(a2,b0,acc[2][0]); acc[2][1]=fmaf(a2,b1,acc[2][1]); acc[2][2]=fmaf(a2,b2,acc[2][2]); acc[2][3]=fmaf(a2,b3,acc[2][3]);
            acc[3][0]=fmaf(a3,b0,acc[3][0]); acc[3][1]=fmaf(a3,b1,acc[3][1]); acc[3][2]=fmaf(a3,b2,acc[3][2]); acc[3][3]=fmaf(a3,b3,acc[3][3]);
        }
        __syncthreads();
    }

    float x20 = g_x2[b*NPTS + j0 + tj*4 + 0];
    float x21 = g_x2[b*NPTS + j0 + tj*4 + 1];
    float x22 = g_x2[b*NPTS + j0 + tj*4 + 2];
    float x23 = g_x2[b*NPTS + j0 + tj*4 + 3];
    #pragma unroll
    for (int a = 0; a < 4; a++) {
        int i = i0 + ti*4 + a;
        float r2 = g_r2[i];
        float4 o;
        o.x = sqrtf(fmaxf(r2 + x20 - 2.f*acc[a][0], 0.f));
        o.y = sqrtf(fmaxf(r2 + x21 - 2.f*acc[a][1], 0.f));
        o.z = sqrtf(fmaxf(r2 + x22 - 2.f*acc[a][2], 0.f));
        o.w = sqrtf(fmaxf(r2 + x23 - 2.f*acc[a][3], 0.f));
        *(float4*)(&g_C[((size_t)b*NREF + i)*NPTS + j0 + tj*4]) = o;
    }
}

// -------- cluster Sinkhorn with sparse candidate lists --------
__global__ __launch_bounds__(1024, 1) __cluster_dims__(2, 1, 1)
void sinkhorn_cluster() {
    __shared__ __align__(16) float us[NREF];
    __shared__ __align__(16) float vs[NPTS];
    __shared__ float red[32];
    __shared__ float dm2[2];

    int b    = blockIdx.x >> 1;
    int rank = blockIdx.x & 1;
    int peer = rank ^ 1;
    int tid = threadIdx.x, lane = tid & 31, w = tid >> 5;
    const float* Cb = g_C + (size_t)b * NREF * NPTS;

    unsigned int us_a = smem_u32(us);
    unsigned int vs_a = smem_u32(vs);
    unsigned int dm_a = smem_u32(dm2);

    if (tid < NREF) us[tid] = 0.f;
    vs[tid] = 0.f; vs[tid + 1024] = 0.f;
    __syncthreads();
    cluster_sync_();

    float A = 1e30f;           // accumulated drift since last rebuild (uniform)
    bool lists_valid = false;  // uniform across cluster

    for (int iter = 0; iter < ITERS; iter++) {
        bool sparse  = lists_valid && (A < ALIM);
        bool rebuild = !sparse && (A < RBLIM);
        float dmax = 0.f;

        // ================= u phase: warp w -> rows rank*128 + w*4 .. +3 ==========
        #pragma unroll 1
        for (int r = 0; r < 4; r++) {
            int i = rank * 128 + w * 4 + r;
            int rowg = b * NREF + i;
            float nu;
            int cnt = sparse ? g_rcnt[rowg] : -1;
            if (sparse && cnt >= 0) {
                float z = NEG_INF;
                int jj = 0;
                if (lane < cnt) {
                    jj = g_ridx[(size_t)rowg*RK + lane];
                    z  = vs[jj] - g_rval[(size_t)rowg*RK + lane];
                }
                float m = z;
                #pragma unroll
                for (int o = 16; o; o >>= 1) m = fmaxf(m, __shfl_xor_sync(FULLM, m, o));
                float e = (z > m - 25.f) ? __expf(z - m) : 0.f;
                #pragma unroll
                for (int o = 16; o; o >>= 1) e += __shfl_xor_sync(FULLM, e, o);
                nu = LOG_WX - (m + __logf(e));
            } else {
                const float4* Crow = (const float4*)(Cb + (size_t)i * NPTS);
                float m = NEG_INF, s = 0.f;
                #pragma unroll 4
                for (int k = lane; k < NPTS/4; k += 32) {
                    float4 c  = Crow[k];
                    float4 vv = *(const float4*)&vs[k*4];
                    float z0 = fmaf(-SCALE, c.x, vv.x);
                    float z1 = fmaf(-SCALE, c.y, vv.y);
                    float z2 = fmaf(-SCALE, c.z, vv.z);
                    float z3 = fmaf(-SCALE, c.w, vv.w);
                    float lm = fmaxf(fmaxf(z0, z1), fmaxf(z2, z3));
                    if (lm > m - 25.f) {
                        float nm = fmaxf(m, lm);
                        s *= __expf(m - nm);
                        if (z0 > nm - 25.f) s += __expf(z0 - nm);
                        if (z1 > nm - 25.f) s += __expf(z1 - nm);
                        if (z2 > nm - 25.f) s += __expf(z2 - nm);
                        if (z3 > nm - 25.f) s += __expf(z3 - nm);
                        m = nm;
                    }
                }
                #pragma unroll
                for (int o = 16; o; o >>= 1) {
                    float mo = __shfl_xor_sync(FULLM, m, o);
                    float so = __shfl_xor_sync(FULLM, s, o);
                    float nm = fmaxf(m, mo);
                    s = s * __expf(m - nm) + so * __expf(mo - nm);
                    m = nm;
                }
                nu = LOG_WX - (m + __logf(s));

                if (rebuild) {
                    float thr = m - MARGIN;
                    int base = 0;
                    for (int k = lane; k < NPTS/4; k += 32) {
                        float4 c  = Crow[k];
                        float4 vv = *(const float4*)&vs[k*4];
                        float cs[4] = {SCALE*c.x, SCALE*c.y, SCALE*c.z, SCALE*c.w};
                        float zz[4] = {vv.x - cs[0], vv.y - cs[1], vv.z - cs[2], vv.w - cs[3]};
                        #pragma unroll
                        for (int q = 0; q < 4; q++) {
                            bool t = zz[q] > thr;
                            unsigned mk = __ballot_sync(FULLM, t);
                            if (mk) {
                                int pos = base + __popc(mk & ((1u << lane) - 1u));
                                if (t && pos < RK) {
                                    g_ridx[(size_t)rowg*RK + pos] = (unsigned short)(k*4 + q);
                                    g_rval[(size_t)rowg*RK + pos] = cs[q];
                                }
                                base += __popc(mk);
                            }
                        }
                    }
                    if (lane == 0) g_rcnt[rowg] = (base <= RK) ? base : -1;
                } else if (!sparse) {
                    if (lane == 0) g_rcnt[rowg] = -1;   // invalidate
                }
            }
            if (lane == 0) {
                dmax = fmaxf(dmax, fabsf(nu - us[i]));
                us[i] = nu;
                st_peer_f32(us_a + 4u*i, peer, nu);
            }
        }
        __syncthreads();
        cluster_sync_();

        // ================= v phase: thread -> col rank*1024 + tid ================
        {
            int j = rank * 1024 + tid;
            int colg = b * NPTS + j;
            float nv;
            int cnt = sparse ? g_ccnt[colg] : -1;
            if (sparse && cnt >= 0) {
                float m = NEG_INF, s = 0.f;
                for (int k = 0; k < cnt; k++) {
                    float cs = g_cval[(size_t)(b*CK + k) * NPTS + j];
                    int   ii = g_cidx[(size_t)(b*CK + k) * NPTS + j];
                    float z = us[ii] - cs;
                    if (z > m - 25.f) {
                        float nm = fmaxf(m, z);
                        s = s * __expf(m - nm) + __expf(z - nm);
                        m = nm;
                    }
                }
                nv = LOG_WY - (m + __logf(s));
            } else {
                const float* Cp = Cb + j;
                float m = NEG_INF, s = 0.f;
                for (int i0 = 0; i0 < NREF; i0 += 8) {
                    float c[8];
                    #pragma unroll
                    for (int q = 0; q < 8; q++)
                        c[q] = Cp[(size_t)(i0 + q) * NPTS];
                    #pragma unroll
                    for (int q = 0; q < 8; q++) {
                        float z = fmaf(-SCALE, c[q], us[i0 + q]);
                        if (z > m - 25.f) {
                            float nm = fmaxf(m, z);
                            s = s * __expf(m - nm) + __expf(z - nm);
                            m = nm;
                        }
                    }
                }
                nv = LOG_WY - (m + __logf(s));

                if (rebuild) {
                    float thr = m - MARGIN;
                    int k2 = 0;
                    for (int i0 = 0; i0 < NREF; i0++) {
                        float cs = SCALE * Cp[(size_t)i0 * NPTS];
                        float z = us[i0] - cs;
                        if (z > thr) {
                            if (k2 < CK) {
                                g_cval[(size_t)(b*CK + k2) * NPTS + j] = cs;
                                g_cidx[(size_t)(b*CK + k2) * NPTS + j] = (unsigned char)i0;
                            }
                            k2++;
                        }
                    }
                    g_ccnt[colg] = (k2 <= CK) ? k2 : -1;
                } else if (!sparse) {
                    g_ccnt[colg] = -1;
                }
            }
            dmax = fmaxf(dmax, fabsf(nv - vs[j]));
            vs[j] = nv;
            st_peer_f32(vs_a + 4u*j, peer, nv);
        }

        // ================= dmax reduction + exchange + control ==================
        #pragma unroll
        for (int o = 16; o; o >>= 1) dmax = fmaxf(dmax, __shfl_xor_sync(FULLM, dmax, o));
        if (lane == 0) red[w] = dmax;
        __syncthreads();
        if (tid == 0) {
            float dm = 0.f;
            #pragma unroll
            for (int q = 0; q < 32; q++) dm = fmaxf(dm, red[q]);
            dm2[rank] = dm;
            st_peer_f32(dm_a + 4u*rank, peer, dm);
        }
        __syncthreads();
        cluster_sync_();
        float dm = fmaxf(dm2[0], dm2[1]);
        if (rebuild) lists_valid = true;
        else if (!sparse) lists_valid = false;
        A = sparse ? (A + dm) : dm;
        if (dm < TOLS) break;
    }

    if (rank == 0) {
        if (tid < NREF) g_us[b*NREF + tid] = us[tid];
        g_vs[b*NPTS + tid]        = vs[tid];
        g_vs[b*NPTS + tid + 1024] = vs[tid + 1024];
    }
    cluster_sync_();
}

// -------- barycenters from row candidate lists (dense fallback) --------
__global__ __launch_bounds__(256) void bary_kernel(const float* __restrict__ X,
                                                   const float* __restrict__ REF,
                                                   float* __restrict__ out) {
    int b = blockIdx.y, tid = threadIdx.x, lane = tid & 31, w = tid >> 5;
    int i = blockIdx.x * 8 + w;
    int rowg = b * NREF + i;
    float ui = g_us[rowg];
    const float* Xb = X + (size_t)b * NPTS * DIM;
    const float* vrow = g_vs + b * NPTS;

    float acc0 = 0.f, acc1 = 0.f, acc2 = 0.f, acc3 = 0.f, den = 0.f;
    int cnt = g_rcnt[rowg];
    if (cnt >= 0) {
        float wabs = 0.f; int jj = 0;
        if (lane < cnt) {
            jj = g_ridx[(size_t)rowg*RK + lane];
            float cs = g_rval[(size_t)rowg*RK + lane];
            float z = ui + vrow[jj] - cs;
            if (z > -40.f) wabs = __expf(z);
        }
        unsigned act = __ballot_sync(FULLM, wabs > 0.f);
        while (act) {
            int p = __ffs(act) - 1; act &= act - 1;
            float wj = __shfl_sync(FULLM, wabs, p);
            int   jp = __shfl_sync(FULLM, jj, p);
            const float* xr = Xb + (size_t)jp * DIM;
            acc0 = fmaf(wj, xr[lane     ], acc0);
            acc1 = fmaf(wj, xr[lane + 32], acc1);
            acc2 = fmaf(wj, xr[lane + 64], acc2);
            acc3 = fmaf(wj, xr[lane + 96], acc3);
            den += wj;
        }
    } else {
        const float* Crow = g_C + ((size_t)b*NREF + i) * NPTS;
        for (int jb = 0; jb < NPTS; jb += 32) {
            int j = jb + lane;
            float z = fmaf(-SCALE, Crow[j], ui + vrow[j]);
            float wgt = 0.f;
            if (z > -40.f) wgt = __expf(z);
            unsigned act = __ballot_sync(FULLM, z > -40.f);
            while (act) {
                int p = __ffs(act) - 1; act &= act - 1;
                float wj = __shfl_sync(FULLM, wgt, p);
                const float* xr = Xb + (size_t)(jb + p) * DIM;
                acc0 = fmaf(wj, xr[lane     ], acc0);
                acc1 = fmaf(wj, xr[lane + 32], acc1);
                acc2 = fmaf(wj, xr[lane + 64], acc2);
                acc3 = fmaf(wj, xr[lane + 96], acc3);
                den += wj;
            }
        }
    }
    float inv = 1.f / (den + 1e-8f);
    float* orow = out + ((size_t)b*NREF + i) * DIM;
    orow[lane     ] = acc0 * inv - REF[i*DIM + lane     ];
    orow[lane + 32] = acc1 * inv - REF[i*DIM + lane + 32];
    orow[lane + 64] = acc2 * inv - REF[i*DIM + lane + 64];
    orow[lane + 96] = acc3 * inv - REF[i*DIM + lane + 96];
}

extern "C" void kernel_launch(void* const* d_in, const int* in_sizes, int n_in,
                              void* d_out, int out_size) {
    const float* a = (const float*)d_in[0];
    const float* c = (const float*)d_in[1];
    const float *X, *REF;
    if (in_sizes[0] == NREF * DIM) { REF = a; X = c; }
    else                           { X = a;  REF = c; }
    float* out = (float*)d_out;

    int warps = B_*NPTS + NREF;
    aux_kernel<<<(warps*32 + 255) / 256, 256>>>(X, REF);

    dim3 cg(NPTS/64, NREF/64, B_);
    c_kernel<<<cg, 256>>>(X, REF);

    sinkhorn_cluster<<<2 * B_, 1024>>>();

    bary_kernel<<<dim3(NREF/8, B_), 256>>>(X, REF, out);
}

// round 6
// speedup vs baseline: 1.1133x; 1.1133x over previous
#include <cuda_runtime.h>
#include <cstdint>
#include <math.h>

#define B_    64
#define NREF  256
#define NPTS  2048
#define DIM   128
#define SCALE 1000.0f
#define LOG_WX (-5.5451748845f)   /* log(1/256 + 1e-8)  */
#define LOG_WY (-7.6245985065f)   /* log(1/2048 + 1e-8) */
#define ITERS 100
#define FULLM 0xffffffffu
#define NEG_INF __int_as_float(0xff800000)
#define TOLS  0.02f
#define MAGU  0x4B000000u         /* 2^23 float magic for u16->f32 */
#define HMAG  4194304.0f          /* 2^22 = 0.5 * 2^23 */
#define SMARG 25.0f               /* screen margin (scaled units) */

// -------- device scratch (allocation-free per harness rules) --------
__device__ float g_C [(size_t)B_ * NREF * NPTS];                    // exact cost (scaled /1000)
__device__ __align__(16) unsigned short g_Cq[(size_t)B_ * NREF * NPTS]; // q = round(2000*dist)
__device__ float g_us[B_ * NREF];
__device__ float g_vs[B_ * NPTS];
__device__ float g_x2[B_ * NPTS];
__device__ float g_r2[NREF];

__device__ __forceinline__ unsigned int smem_u32(const void* p) {
    unsigned int a;
    asm("{ .reg .u64 t; cvta.to.shared.u64 t, %1; cvt.u32.u64 %0, t; }" : "=r"(a) : "l"(p));
    return a;
}
__device__ __forceinline__ void st_peer_f32(unsigned int local_addr, int peer, float v) {
    unsigned int rem;
    asm volatile("mapa.shared::cluster.u32 %0, %1, %2;" : "=r"(rem) : "r"(local_addr), "r"(peer));
    asm volatile("st.shared::cluster.f32 [%0], %1;" :: "r"(rem), "f"(v) : "memory");
}
__device__ __forceinline__ void cluster_sync_() {
    asm volatile("barrier.cluster.arrive.aligned;" ::: "memory");
    asm volatile("barrier.cluster.wait.aligned;" ::: "memory");
}

// -------- squared norms --------
__global__ void aux_kernel(const float* __restrict__ X, const float* __restrict__ REF) {
    int gw   = (blockIdx.x * blockDim.x + threadIdx.x) >> 5;
    int lane = threadIdx.x & 31;
    if (gw < B_ * NPTS) {
        const float* r = X + (size_t)gw * DIM;
        float s = 0.f;
        #pragma unroll
        for (int k = lane; k < DIM; k += 32) { float t = r[k]; s = fmaf(t, t, s); }
        #pragma unroll
        for (int o = 16; o; o >>= 1) s += __shfl_xor_sync(FULLM, s, o);
        if (!lane) g_x2[gw] = s;
    } else if (gw < B_ * NPTS + NREF) {
        int i = gw - B_ * NPTS;
        const float* r = REF + i * DIM;
        float s = 0.f;
        #pragma unroll
        for (int k = lane; k < DIM; k += 32) { float t = r[k]; s = fmaf(t, t, s); }
        #pragma unroll
        for (int o = 16; o; o >>= 1) s += __shfl_xor_sync(FULLM, s, o);
        if (!lane) g_r2[i] = s;
    }
}

// -------- C + Cq build --------
__global__ __launch_bounds__(256) void c_kernel(const float* __restrict__ X,
                                                const float* __restrict__ REF) {
    __shared__ float sA[32][65];
    __shared__ float sB[32][65];
    int b  = blockIdx.z;
    int i0 = blockIdx.y * 64, j0 = blockIdx.x * 64;
    int tid = threadIdx.x;
    int ti = tid >> 4, tj = tid & 15;
    const float* Xb = X + (size_t)b * NPTS * DIM;

    float acc[4][4];
    #pragma unroll
    for (int a = 0; a < 4; a++)
        #pragma unroll
        for (int c = 0; c < 4; c++) acc[a][c] = 0.f;

    for (int k0 = 0; k0 < DIM; k0 += 32) {
        #pragma unroll
        for (int r = 0; r < 8; r++) {
            int e  = r * 256 + tid;
            int ii = e >> 5, kk = e & 31;
            sA[kk][ii] = REF[(i0 + ii) * DIM + k0 + kk];
            sB[kk][ii] = Xb[(size_t)(j0 + ii) * DIM + k0 + kk];
        }
        __syncthreads();
        #pragma unroll
        for (int kk = 0; kk < 32; kk++) {
            float a0 = sA[kk][ti*4+0], a1 = sA[kk][ti*4+1], a2 = sA[kk][ti*4+2], a3 = sA[kk][ti*4+3];
            float b0 = sB[kk][tj*4+0], b1 = sB[kk][tj*4+1], b2 = sB[kk][tj*4+2], b3 = sB[kk][tj*4+3];
            acc[0][0]=fmaf(a0,b0,acc[0][0]); acc[0][1]=fmaf(a0,b1,acc[0][1]); acc[0][2]=fmaf(a0,b2,acc[0][2]); acc[0][3]=fmaf(a0,b3,acc[0][3]);
            acc[1][0]=fmaf(a1,b0,acc[1][0]); acc[1][1]=fmaf(a1,b1,acc[1][1]); acc[1][2]=fmaf(a1,b2,acc[1][2]); acc[1][3]=fmaf(a1,b3,acc[1][3]);
            acc[2][0]=fmaf(a2,b0,acc[2][0]); acc[2][1]=fmaf(a2,b1,acc[2][1]); acc[2][2]=fmaf(a2,b2,acc[2][2]); acc[2][3]=fmaf(a2,b3,acc[2][3]);
            acc[3][0]=fmaf(a3,b0,acc[3][0]); acc[3][1]=fmaf(a3,b1,acc[3][1]); acc[3][2]=fmaf(a3,b2,acc[3][2]); acc[3][3]=fmaf(a3,b3,acc[3][3]);
        }
        __syncthreads();
    }

    float x20 = g_x2[b*NPTS + j0 + tj*4 + 0];
    float x21 = g_x2[b*NPTS + j0 + tj*4 + 1];
    float x22 = g_x2[b*NPTS + j0 + tj*4 + 2];
    float x23 = g_x2[b*NPTS + j0 + tj*4 + 3];
    #pragma unroll
    for (int a = 0; a < 4; a++) {
        int i = i0 + ti*4 + a;
        float r2 = g_r2[i];
        float4 o;
        o.x = sqrtf(fmaxf(r2 + x20 - 2.f*acc[a][0], 0.f));
        o.y = sqrtf(fmaxf(r2 + x21 - 2.f*acc[a][1], 0.f));
        o.z = sqrtf(fmaxf(r2 + x22 - 2.f*acc[a][2], 0.f));
        o.w = sqrtf(fmaxf(r2 + x23 - 2.f*acc[a][3], 0.f));
        size_t idx = ((size_t)b*NREF + i)*NPTS + j0 + tj*4;
        *(float4*)(&g_C[idx]) = o;
        ushort4 q;
        q.x = (unsigned short)__float2uint_rn(fminf(2000.f*o.x, 65535.f));
        q.y = (unsigned short)__float2uint_rn(fminf(2000.f*o.y, 65535.f));
        q.z = (unsigned short)__float2uint_rn(fminf(2000.f*o.z, 65535.f));
        q.w = (unsigned short)__float2uint_rn(fminf(2000.f*o.w, 65535.f));
        *(ushort4*)(&g_Cq[idx]) = q;
    }
}

// -------- cluster Sinkhorn: screen on u16 Cq (L2-resident), exact fp32 refine --------
// CTA rank owns rows [128r, 128r+128). u-phase: row LSE. v-phase: column partial
// LSE over own rows, partials merged across the cluster (1 barrier per iteration).
__global__ __launch_bounds__(1024, 1) __cluster_dims__(2, 1, 1)
void sinkhorn_cluster() {
    __shared__ __align__(16) float us [NREF];
    __shared__ __align__(16) float usb[NREF];    // us + 2^22 (screen operand)
    __shared__ __align__(16) float vs [NPTS];
    __shared__ __align__(16) float vsb[NPTS];    // vs + 2^22
    __shared__ __align__(16) float pmP[NPTS];    // peer partial max
    __shared__ __align__(16) float psP[NPTS];    // peer partial sum
    __shared__ float red[32];
    __shared__ float s_dmu;      // own u-dmax
    __shared__ float s_dmuP;     // peer u-dmax (pushed)
    __shared__ int   s_done;

    int b    = blockIdx.x >> 1;
    int rank = blockIdx.x & 1;
    int peer = rank ^ 1;
    int tid = threadIdx.x, lane = tid & 31, w = tid >> 5;
    const float*          Cb  = g_C  + (size_t)b * NREF * NPTS;
    const unsigned short* Cqb = g_Cq + (size_t)b * NREF * NPTS;

    unsigned int pm_a  = smem_u32(pmP);
    unsigned int ps_a  = smem_u32(psP);
    unsigned int dmu_a = smem_u32(&s_dmuP);

    if (tid < NREF) { us[tid] = 0.f; usb[tid] = HMAG; }
    vs[tid] = 0.f;  vs[tid + 1024] = 0.f;
    vsb[tid] = HMAG; vsb[tid + 1024] = HMAG;
    __syncthreads();

    for (int iter = 0; iter < ITERS; iter++) {
        // ======== u phase: warp w -> rows rank*128 + w*4 .. +3 ========
        float udmax = 0.f;
        #pragma unroll 1
        for (int r = 0; r < 4; r++) {
            int i = rank * 128 + w * 4 + r;
            const uint4* rq = (const uint4*)(Cqb + (size_t)i * NPTS);
            const float* Crow = Cb + (size_t)i * NPTS;
            float m = NEG_INF, s = 0.f;
            float mt = NEG_INF, thr = NEG_INF;
            #pragma unroll 2
            for (int t = 0; t < 8; t++) {
                int q4 = lane + 32*t;
                uint4 wd = rq[q4];
                int j0 = q4 * 8;
                float4 va = *(const float4*)&vsb[j0];
                float4 vb = *(const float4*)&vsb[j0 + 4];
                unsigned wds[4] = {wd.x, wd.y, wd.z, wd.w};
                float vv[8] = {va.x,va.y,va.z,va.w, vb.x,vb.y,vb.z,vb.w};
                #pragma unroll
                for (int h = 0; h < 4; h++) {
                    float f0 = __uint_as_float(MAGU | (wds[h] & 0xFFFFu));
                    float f1 = __uint_as_float(MAGU | (wds[h] >> 16));
                    float z0 = fmaf(-0.5f, f0, vv[2*h]);
                    float z1 = fmaf(-0.5f, f1, vv[2*h+1]);
                    if (z0 > thr) {
                        mt = fmaxf(mt, z0); thr = mt - SMARG;
                        float c  = __ldcs(Crow + (j0 + 2*h));
                        float zx = fmaf(-SCALE, c, vs[j0 + 2*h]);
                        float nm = fmaxf(m, zx);
                        s = s * __expf(m - nm) + __expf(zx - nm);
                        m = nm;
                    }
                    if (z1 > thr) {
                        mt = fmaxf(mt, z1); thr = mt - SMARG;
                        float c  = __ldcs(Crow + (j0 + 2*h + 1));
                        float zx = fmaf(-SCALE, c, vs[j0 + 2*h + 1]);
                        float nm = fmaxf(m, zx);
                        s = s * __expf(m - nm) + __expf(zx - nm);
                        m = nm;
                    }
                }
            }
            #pragma unroll
            for (int o = 16; o; o >>= 1) {
                float mo = __shfl_xor_sync(FULLM, m, o);
                float so = __shfl_xor_sync(FULLM, s, o);
                float nm = fmaxf(m, mo);
                s = s * __expf(m - nm) + so * __expf(mo - nm);
                m = nm;
            }
            float nu = LOG_WX - (m + __logf(s));
            if (lane == 0) {
                udmax = fmaxf(udmax, fabsf(nu - us[i]));
                us[i]  = nu;
                usb[i] = nu + HMAG;
            }
        }
        if (lane == 0) red[w] = udmax;
        __syncthreads();          // us/usb ready for v-partials
        if (tid == 0) {
            float dm = 0.f;
            #pragma unroll
            for (int q = 0; q < 32; q++) dm = fmaxf(dm, red[q]);
            s_dmu = dm;
        }

        // ======== v partials over OWN rows: thread -> cols 2*tid, 2*tid+1 ========
        int j0 = 2 * tid;
        const unsigned* cq32 = (const unsigned*)Cqb;
        float m0 = NEG_INF, s0 = 0.f, thr0 = NEG_INF, mt0 = NEG_INF;
        float m1 = NEG_INF, s1 = 0.f, thr1 = NEG_INF, mt1 = NEG_INF;
        int ibase = rank * 128;
        #pragma unroll 1
        for (int ii = 0; ii < 128; ii += 4) {
            unsigned wrd[4];
            #pragma unroll
            for (int k = 0; k < 4; k++)
                wrd[k] = cq32[(size_t)(ibase + ii + k) * (NPTS/2) + tid];
            #pragma unroll
            for (int k = 0; k < 4; k++) {
                int i = ibase + ii + k;
                float ub = usb[i];
                float f0 = __uint_as_float(MAGU | (wrd[k] & 0xFFFFu));
                float f1 = __uint_as_float(MAGU | (wrd[k] >> 16));
                float z0 = fmaf(-0.5f, f0, ub);
                float z1 = fmaf(-0.5f, f1, ub);
                if (z0 > thr0) {
                    mt0 = fmaxf(mt0, z0); thr0 = mt0 - SMARG;
                    float c  = __ldcs(Cb + (size_t)i * NPTS + j0);
                    float zx = fmaf(-SCALE, c, us[i]);
                    float nm = fmaxf(m0, zx);
                    s0 = s0 * __expf(m0 - nm) + __expf(zx - nm);
                    m0 = nm;
                }
                if (z1 > thr1) {
                    mt1 = fmaxf(mt1, z1); thr1 = mt1 - SMARG;
                    float c  = __ldcs(Cb + (size_t)i * NPTS + j0 + 1);
                    float zx = fmaf(-SCALE, c, us[i]);
                    float nm = fmaxf(m1, zx);
                    s1 = s1 * __expf(m1 - nm) + __expf(zx - nm);
                    m1 = nm;
                }
            }
        }
        // push partials (and u-dmax) to peer
        st_peer_f32(pm_a + 4u*j0,       peer, m0);
        st_peer_f32(ps_a + 4u*j0,       peer, s0);
        st_peer_f32(pm_a + 4u*(j0+1),   peer, m1);
        st_peer_f32(ps_a + 4u*(j0+1),   peer, s1);
        if (tid == 0) st_peer_f32(dmu_a, peer, s_dmu);

        cluster_sync_();          // publish partials both ways

        // ======== merge partials -> full v (computed identically on both CTAs) ====
        float vdm;
        {
            float pm = pmP[j0], ps = psP[j0];
            float M  = fmaxf(m0, pm);
            float S  = s0 * __expf(m0 - M) + ps * __expf(pm - M);
            float nv0 = LOG_WY - (M + __logf(S));
            float pm2 = pmP[j0+1], ps2 = psP[j0+1];
            float M2  = fmaxf(m1, pm2);
            float S2  = s1 * __expf(m1 - M2) + ps2 * __expf(pm2 - M2);
            float nv1 = LOG_WY - (M2 + __logf(S2));
            vdm = fmaxf(fabsf(nv0 - vs[j0]), fabsf(nv1 - vs[j0+1]));
            vs[j0]     = nv0;  vsb[j0]     = nv0 + HMAG;
            vs[j0+1]   = nv1;  vsb[j0+1]   = nv1 + HMAG;
        }

        // ======== convergence: max(u-dm own, u-dm peer, v-dm) ========
        #pragma unroll
        for (int o = 16; o; o >>= 1) vdm = fmaxf(vdm, __shfl_xor_sync(FULLM, vdm, o));
        if (lane == 0) red[w] = vdm;
        __syncthreads();
        if (tid == 0) {
            float dm = 0.f;
            #pragma unroll
            for (int q = 0; q < 32; q++) dm = fmaxf(dm, red[q]);
            dm = fmaxf(dm, fmaxf(s_dmu, s_dmuP));
            s_done = (dm < TOLS) ? 1 : 0;
        }
        __syncthreads();          // also orders vs/vsb writes before next u-pass
        if (s_done) break;
    }

    // export: each rank its own u half; rank 0 exports full v
    if (tid < 128) g_us[b*NREF + rank*128 + tid] = us[rank*128 + tid];
    if (rank == 0) {
        g_vs[b*NPTS + tid]        = vs[tid];
        g_vs[b*NPTS + tid + 1024] = vs[tid + 1024];
    }
    cluster_sync_();   // keep SMEM alive until peer's last pushes complete
}

// -------- barycenters: Cq screen + exact fp32 weights + ballot X gather --------
__global__ __launch_bounds__(256) void bary_kernel(const float* __restrict__ X,
                                                   const float* __restrict__ REF,
                                                   float* __restrict__ out) {
    __shared__ float vsE[NPTS];
    __shared__ float vsS[NPTS];
    int b = blockIdx.y, tid = threadIdx.x, lane = tid & 31, w = tid >> 5;
    const float* vrow = g_vs + b * NPTS;
    #pragma unroll
    for (int r = 0; r < NPTS/256; r++) {
        float v = vrow[r*256 + tid];
        vsE[r*256 + tid] = v;
        vsS[r*256 + tid] = v + HMAG;
    }
    __syncthreads();

    int i = blockIdx.x * 8 + w;
    float ui = g_us[b*NREF + i];
    const float*          Crow = g_C  + ((size_t)b*NREF + i) * NPTS;
    const unsigned short* Cqr  = g_Cq + ((size_t)b*NREF + i) * NPTS;
    const float* Xb = X + (size_t)b * NPTS * DIM;

    float acc0 = 0.f, acc1 = 0.f, acc2 = 0.f, acc3 = 0.f, den = 0.f;
    for (int jb = 0; jb < NPTS; jb += 32) {
        int j = jb + lane;
        unsigned q = Cqr[j];
        float f = __uint_as_float(MAGU | q);
        float zt = fmaf(-0.5f, f, ui + vsS[j]);   // approx z, slack <= ~0.4
        float wgt = 0.f;
        bool flag = zt > -61.f;
        if (flag) {
            float c = __ldcs(Crow + j);
            float z = fmaf(-SCALE, c, ui + vsE[j]);
            wgt = __expf(z);
        }
        unsigned act = __ballot_sync(FULLM, flag);
        while (act) {
            int p = __ffs(act) - 1; act &= act - 1;
            float wj = __shfl_sync(FULLM, wgt, p);
            const float* xr = Xb + (size_t)(jb + p) * DIM;
            acc0 = fmaf(wj, xr[lane     ], acc0);
            acc1 = fmaf(wj, xr[lane + 32], acc1);
            acc2 = fmaf(wj, xr[lane + 64], acc2);
            acc3 = fmaf(wj, xr[lane + 96], acc3);
            den += wj;
        }
    }
    float inv = 1.f / (den + 1e-8f);
    float* orow = out + ((size_t)b*NREF + i) * DIM;
    orow[lane     ] = acc0 * inv - REF[i*DIM + lane     ];
    orow[lane + 32] = acc1 * inv - REF[i*DIM + lane + 32];
    orow[lane + 64] = acc2 * inv - REF[i*DIM + lane + 64];
    orow[lane + 96] = acc3 * inv - REF[i*DIM + lane + 96];
}

extern "C" void kernel_launch(void* const* d_in, const int* in_sizes, int n_in,
                              void* d_out, int out_size) {
    const float* a = (const float*)d_in[0];
    const float* c = (const float*)d_in[1];
    const float *X, *REF;
    if (in_sizes[0] == NREF * DIM) { REF = a; X = c; }
    else                           { X = a;  REF = c; }
    float* out = (float*)d_out;

    int warps = B_*NPTS + NREF;
    aux_kernel<<<(warps*32 + 255) / 256, 256>>>(X, REF);

    dim3 cg(NPTS/64, NREF/64, B_);
    c_kernel<<<cg, 256>>>(X, REF);

    sinkhorn_cluster<<<2 * B_, 1024>>>();

    bary_kernel<<<dim3(NREF/8, B_), 256>>>(X, REF, out);
}

// round 7
// speedup vs baseline: 1.9314x; 1.7348x over previous
#include <cuda_runtime.h>
#include <cstdint>
#include <math.h>

#define B_    64
#define NREF  256
#define NPTS  2048
#define DIM   128
#define SCALE 1000.0f
#define LOG_WX (-5.5451748845f)   /* log(1/256 + 1e-8)  */
#define LOG_WY (-7.6245985065f)   /* log(1/2048 + 1e-8) */
#define ITERS 100
#define FULLM 0xffffffffu
#define NEG_INF __int_as_float(0xff800000)
#define TOLS  0.02f

#define STEP   0.00390625f        /* 2^-8, exact */
#define QSCALE 256000.0f          /* 1000 * 256  */
#define QMAXF  8388607.0f         /* 2^23 - 1    */
#define MAGIC  0x4B000000u        /* 2^23 float  */
#define BIASV  32768.0f           /* STEP * 2^23 */

// -------- device scratch (allocation-free per harness rules) --------
__device__ __align__(16) unsigned short g_Clo[(size_t)B_ * NREF * NPTS]; // low 16 bits of q
__device__ __align__(16) unsigned char  g_Chi[(size_t)B_ * NREF * NPTS]; // high 8 bits of q
__device__ float g_us[B_ * NREF];
__device__ float g_vs[B_ * NPTS];
__device__ float g_x2[B_ * NPTS];
__device__ float g_r2[NREF];

__device__ __forceinline__ unsigned int smem_u32(const void* p) {
    unsigned int a;
    asm("{ .reg .u64 t; cvta.to.shared.u64 t, %1; cvt.u32.u64 %0, t; }" : "=r"(a) : "l"(p));
    return a;
}
__device__ __forceinline__ void st_peer_f32(unsigned int local_addr, int peer, float v) {
    unsigned int rem;
    asm volatile("mapa.shared::cluster.u32 %0, %1, %2;" : "=r"(rem) : "r"(local_addr), "r"(peer));
    asm volatile("st.shared::cluster.f32 [%0], %1;" :: "r"(rem), "f"(v) : "memory");
}
__device__ __forceinline__ void cluster_sync_() {
    asm volatile("barrier.cluster.arrive.aligned;" ::: "memory");
    asm volatile("barrier.cluster.wait.aligned;" ::: "memory");
}

// -------- squared norms --------
__global__ void aux_kernel(const float* __restrict__ X, const float* __restrict__ REF) {
    int gw   = (blockIdx.x * blockDim.x + threadIdx.x) >> 5;
    int lane = threadIdx.x & 31;
    if (gw < B_ * NPTS) {
        const float* r = X + (size_t)gw * DIM;
        float s = 0.f;
        #pragma unroll
        for (int k = lane; k < DIM; k += 32) { float t = r[k]; s = fmaf(t, t, s); }
        #pragma unroll
        for (int o = 16; o; o >>= 1) s += __shfl_xor_sync(FULLM, s, o);
        if (!lane) g_x2[gw] = s;
    } else if (gw < B_ * NPTS + NREF) {
        int i = gw - B_ * NPTS;
        const float* r = REF + i * DIM;
        float s = 0.f;
        #pragma unroll
        for (int k = lane; k < DIM; k += 32) { float t = r[k]; s = fmaf(t, t, s); }
        #pragma unroll
        for (int o = 16; o; o >>= 1) s += __shfl_xor_sync(FULLM, s, o);
        if (!lane) g_r2[i] = s;
    }
}

// -------- build 24-bit quantized cost: q = round(256000 * dist) --------
__global__ __launch_bounds__(256) void c_kernel(const float* __restrict__ X,
                                                const float* __restrict__ REF) {
    __shared__ float sA[32][65];
    __shared__ float sB[32][65];
    int b  = blockIdx.z;
    int i0 = blockIdx.y * 64, j0 = blockIdx.x * 64;
    int tid = threadIdx.x;
    int ti = tid >> 4, tj = tid & 15;
    const float* Xb = X + (size_t)b * NPTS * DIM;

    float acc[4][4];
    #pragma unroll
    for (int a = 0; a < 4; a++)
        #pragma unroll
        for (int c = 0; c < 4; c++) acc[a][c] = 0.f;

    for (int k0 = 0; k0 < DIM; k0 += 32) {
        #pragma unroll
        for (int r = 0; r < 8; r++) {
            int e  = r * 256 + tid;
            int ii = e >> 5, kk = e & 31;
            sA[kk][ii] = REF[(i0 + ii) * DIM + k0 + kk];
            sB[kk][ii] = Xb[(size_t)(j0 + ii) * DIM + k0 + kk];
        }
        __syncthreads();
        #pragma unroll
        for (int kk = 0; kk < 32; kk++) {
            float a0 = sA[kk][ti*4+0], a1 = sA[kk][ti*4+1], a2 = sA[kk][ti*4+2], a3 = sA[kk][ti*4+3];
            float b0 = sB[kk][tj*4+0], b1 = sB[kk][tj*4+1], b2 = sB[kk][tj*4+2], b3 = sB[kk][tj*4+3];
            acc[0][0]=fmaf(a0,b0,acc[0][0]); acc[0][1]=fmaf(a0,b1,acc[0][1]); acc[0][2]=fmaf(a0,b2,acc[0][2]); acc[0][3]=fmaf(a0,b3,acc[0][3]);
            acc[1][0]=fmaf(a1,b0,acc[1][0]); acc[1][1]=fmaf(a1,b1,acc[1][1]); acc[1][2]=fmaf(a1,b2,acc[1][2]); acc[1][3]=fmaf(a1,b3,acc[1][3]);
            acc[2][0]=fmaf(a2,b0,acc[2][0]); acc[2][1]=fmaf(a2,b1,acc[2][1]); acc[2][2]=fmaf(a2,b2,acc[2][2]); acc[2][3]=fmaf(a2,b3,acc[2][3]);
            acc[3][0]=fmaf(a3,b0,acc[3][0]); acc[3][1]=fmaf(a3,b1,acc[3][1]); acc[3][2]=fmaf(a3,b2,acc[3][2]); acc[3][3]=fmaf(a3,b3,acc[3][3]);
        }
        __syncthreads();
    }

    float x20 = g_x2[b*NPTS + j0 + tj*4 + 0];
    float x21 = g_x2[b*NPTS + j0 + tj*4 + 1];
    float x22 = g_x2[b*NPTS + j0 + tj*4 + 2];
    float x23 = g_x2[b*NPTS + j0 + tj*4 + 3];
    #pragma unroll
    for (int a = 0; a < 4; a++) {
        int i = i0 + ti*4 + a;
        float r2 = g_r2[i];
        float d0 = sqrtf(fmaxf(r2 + x20 - 2.f*acc[a][0], 0.f));
        float d1 = sqrtf(fmaxf(r2 + x21 - 2.f*acc[a][1], 0.f));
        float d2 = sqrtf(fmaxf(r2 + x22 - 2.f*acc[a][2], 0.f));
        float d3 = sqrtf(fmaxf(r2 + x23 - 2.f*acc[a][3], 0.f));
        unsigned q0 = __float2uint_rn(fminf(QSCALE*d0, QMAXF));
        unsigned q1 = __float2uint_rn(fminf(QSCALE*d1, QMAXF));
        unsigned q2 = __float2uint_rn(fminf(QSCALE*d2, QMAXF));
        unsigned q3 = __float2uint_rn(fminf(QSCALE*d3, QMAXF));
        size_t idx = ((size_t)b*NREF + i)*NPTS + j0 + tj*4;
        ushort4 lo;
        lo.x = (unsigned short)(q0 & 0xFFFF);
        lo.y = (unsigned short)(q1 & 0xFFFF);
        lo.z = (unsigned short)(q2 & 0xFFFF);
        lo.w = (unsigned short)(q3 & 0xFFFF);
        *(ushort4*)(&g_Clo[idx]) = lo;
        uchar4 hi;
        hi.x = (unsigned char)(q0 >> 16);
        hi.y = (unsigned char)(q1 >> 16);
        hi.z = (unsigned char)(q2 >> 16);
        hi.w = (unsigned char)(q3 >> 16);
        *(uchar4*)(&g_Chi[idx]) = hi;
    }
}

// -------- cluster Sinkhorn on L2-resident 24-bit cost --------
// CTA rank owns rows [128r, 128r+128): u row-LSE + v column-partials over own rows,
// partials merged cluster-wide. Two cluster barriers/iter (publish, reuse-safe).
__global__ __launch_bounds__(1024, 1) __cluster_dims__(2, 1, 1)
void sinkhorn_cluster() {
    __shared__ __align__(16) float us [NREF];   // true scaled u (own half valid)
    __shared__ __align__(16) float usb[NREF];   // us + 32768
    __shared__ __align__(16) float vs [NPTS];   // true scaled v (full)
    __shared__ __align__(16) float vsb[NPTS];   // vs + 32768
    __shared__ __align__(16) float pmP[NPTS];   // peer partial max
    __shared__ __align__(16) float psP[NPTS];   // peer partial sum
    __shared__ float red[32];
    __shared__ float s_dmu, s_dmuP;
    __shared__ int   s_done;

    int b    = blockIdx.x >> 1;
    int rank = blockIdx.x & 1;
    int peer = rank ^ 1;
    int tid = threadIdx.x, lane = tid & 31, w = tid >> 5;
    const unsigned short* CbLo = g_Clo + (size_t)b * NREF * NPTS;
    const unsigned char*  CbHi = g_Chi + (size_t)b * NREF * NPTS;

    unsigned int pm_a  = smem_u32(pmP);
    unsigned int ps_a  = smem_u32(psP);
    unsigned int dmu_a = smem_u32(&s_dmuP);

    if (tid < NREF) { us[tid] = 0.f; usb[tid] = BIASV; }
    vs[tid] = 0.f;  vs[tid + 1024] = 0.f;
    vsb[tid] = BIASV; vsb[tid + 1024] = BIASV;
    __syncthreads();

    for (int iter = 0; iter < ITERS; iter++) {
        // ======== u phase: warp w -> rows rank*128 + w*4 .. +3 ========
        float udmax = 0.f;
        #pragma unroll 1
        for (int r = 0; r < 4; r++) {
            int i = rank * 128 + w * 4 + r;
            const uint4* rlo = (const uint4*)(CbLo + (size_t)i * NPTS);
            const uint2* rhi = (const uint2*)(CbHi + (size_t)i * NPTS);
            float m = NEG_INF, s = 0.f;
            #pragma unroll 2
            for (int t = 0; t < 8; t++) {
                int k = lane + 32*t;
                uint4 lo = rlo[k];
                uint2 hv = rhi[k];
                int j0 = k * 8;
                float4 va = *(const float4*)&vsb[j0];
                float4 vb = *(const float4*)&vsb[j0 + 4];
                float f0 = __uint_as_float(MAGIC | ((hv.x << 16) & 0xFF0000u) | (lo.x & 0xFFFFu));
                float f1 = __uint_as_float(MAGIC | ((hv.x <<  8) & 0xFF0000u) | (lo.x >> 16));
                float f2 = __uint_as_float(MAGIC | ( hv.x        & 0xFF0000u) | (lo.y & 0xFFFFu));
                float f3 = __uint_as_float(MAGIC | ((hv.x >>  8) & 0xFF0000u) | (lo.y >> 16));
                float f4 = __uint_as_float(MAGIC | ((hv.y << 16) & 0xFF0000u) | (lo.z & 0xFFFFu));
                float f5 = __uint_as_float(MAGIC | ((hv.y <<  8) & 0xFF0000u) | (lo.z >> 16));
                float f6 = __uint_as_float(MAGIC | ( hv.y        & 0xFF0000u) | (lo.w & 0xFFFFu));
                float f7 = __uint_as_float(MAGIC | ((hv.y >>  8) & 0xFF0000u) | (lo.w >> 16));
                float z0 = fmaf(-STEP, f0, va.x);
                float z1 = fmaf(-STEP, f1, va.y);
                float z2 = fmaf(-STEP, f2, va.z);
                float z3 = fmaf(-STEP, f3, va.w);
                float z4 = fmaf(-STEP, f4, vb.x);
                float z5 = fmaf(-STEP, f5, vb.y);
                float z6 = fmaf(-STEP, f6, vb.z);
                float z7 = fmaf(-STEP, f7, vb.w);
                float lm = fmaxf(fmaxf(fmaxf(z0, z1), fmaxf(z2, z3)),
                                 fmaxf(fmaxf(z4, z5), fmaxf(z6, z7)));
                if (lm > m - 25.f) {                 // rare after warm-up
                    float nm = fmaxf(m, lm);
                    s *= __expf(m - nm);
                    if (z0 > nm - 25.f) s += __expf(z0 - nm);
                    if (z1 > nm - 25.f) s += __expf(z1 - nm);
                    if (z2 > nm - 25.f) s += __expf(z2 - nm);
                    if (z3 > nm - 25.f) s += __expf(z3 - nm);
                    if (z4 > nm - 25.f) s += __expf(z4 - nm);
                    if (z5 > nm - 25.f) s += __expf(z5 - nm);
                    if (z6 > nm - 25.f) s += __expf(z6 - nm);
                    if (z7 > nm - 25.f) s += __expf(z7 - nm);
                    m = nm;
                }
            }
            #pragma unroll
            for (int o = 16; o; o >>= 1) {
                float mo = __shfl_xor_sync(FULLM, m, o);
                float so = __shfl_xor_sync(FULLM, s, o);
                float nm = fmaxf(m, mo);
                s = s * __expf(m - nm) + so * __expf(mo - nm);
                m = nm;
            }
            float nu = LOG_WX - (m + __logf(s));
            if (lane == 0) {
                udmax = fmaxf(udmax, fabsf(nu - us[i]));
                us[i]  = nu;
                usb[i] = nu + BIASV;
            }
        }
        if (lane == 0) red[w] = udmax;
        __syncthreads();          // us/usb own half ready
        if (tid == 0) {
            float dm = 0.f;
            #pragma unroll
            for (int q = 0; q < 32; q++) dm = fmaxf(dm, red[q]);
            s_dmu = dm;
        }

        // ======== v partials over OWN rows: thread -> cols 2*tid, 2*tid+1 ========
        int j0 = 2 * tid;
        float m0 = NEG_INF, s0 = 0.f;
        float m1 = NEG_INF, s1 = 0.f;
        int ibase = rank * 128;
        #pragma unroll 1
        for (int ii = 0; ii < 128; ii += 4) {
            unsigned lo32[4]; unsigned short hi16[4];
            #pragma unroll
            for (int k = 0; k < 4; k++) {
                int i = ibase + ii + k;
                lo32[k] = ((const unsigned*)(CbLo + (size_t)i * NPTS))[tid];
                hi16[k] = ((const unsigned short*)(CbHi + (size_t)i * NPTS))[tid];
            }
            #pragma unroll
            for (int k = 0; k < 4; k++) {
                int i = ibase + ii + k;
                float ub = usb[i];
                float f0 = __uint_as_float(MAGIC | (((unsigned)hi16[k] << 16) & 0xFF0000u) | (lo32[k] & 0xFFFFu));
                float f1 = __uint_as_float(MAGIC | (((unsigned)hi16[k] <<  8) & 0xFF0000u) | (lo32[k] >> 16));
                float z0 = fmaf(-STEP, f0, ub);
                float z1 = fmaf(-STEP, f1, ub);
                if (z0 > m0 - 25.f) {
                    float nm = fmaxf(m0, z0);
                    s0 = s0 * __expf(m0 - nm) + __expf(z0 - nm);
                    m0 = nm;
                }
                if (z1 > m1 - 25.f) {
                    float nm = fmaxf(m1, z1);
                    s1 = s1 * __expf(m1 - nm) + __expf(z1 - nm);
                    m1 = nm;
                }
            }
        }
        // push partials + own u-dmax to peer
        st_peer_f32(pm_a + 4u*j0,     peer, m0);
        st_peer_f32(ps_a + 4u*j0,     peer, s0);
        st_peer_f32(pm_a + 4u*(j0+1), peer, m1);
        st_peer_f32(ps_a + 4u*(j0+1), peer, s1);
        if (tid == 0) st_peer_f32(dmu_a, peer, s_dmu);

        cluster_sync_();          // (1) publish partials both ways

        // ======== merge partials -> full v (identical on both CTAs) ========
        float vdm;
        {
            float pm = pmP[j0], ps = psP[j0];
            float M  = fmaxf(m0, pm);
            float S  = s0 * __expf(m0 - M) + ps * __expf(pm - M);
            float nv0 = LOG_WY - (M + __logf(S));
            float pm2 = pmP[j0+1], ps2 = psP[j0+1];
            float M2  = fmaxf(m1, pm2);
            float S2  = s1 * __expf(m1 - M2) + ps2 * __expf(pm2 - M2);
            float nv1 = LOG_WY - (M2 + __logf(S2));
            vdm = fmaxf(fabsf(nv0 - vs[j0]), fabsf(nv1 - vs[j0+1]));
            vs[j0]   = nv0;  vsb[j0]   = nv0 + BIASV;
            vs[j0+1] = nv1;  vsb[j0+1] = nv1 + BIASV;
        }

        // ======== convergence ========
        #pragma unroll
        for (int o = 16; o; o >>= 1) vdm = fmaxf(vdm, __shfl_xor_sync(FULLM, vdm, o));
        if (lane == 0) red[w] = vdm;
        __syncthreads();
        if (tid == 0) {
            float dm = 0.f;
            #pragma unroll
            for (int q = 0; q < 32; q++) dm = fmaxf(dm, red[q]);
            dm = fmaxf(dm, fmaxf(s_dmu, s_dmuP));
            s_done = (dm < TOLS) ? 1 : 0;
        }
        cluster_sync_();          // (2) merges done -> partial buffers reusable; s_done visible
        if (s_done) break;
    }

    // export: each rank its own u half; rank 0 exports full v
    if (tid < 128) g_us[b*NREF + rank*128 + tid] = us[rank*128 + tid];
    if (rank == 0) {
        g_vs[b*NPTS + tid]        = vs[tid];
        g_vs[b*NPTS + tid + 1024] = vs[tid + 1024];
    }
    cluster_sync_();
}

// -------- barycenters: quantized weights + ballot X gather --------
__global__ __launch_bounds__(256) void bary_kernel(const float* __restrict__ X,
                                                   const float* __restrict__ REF,
                                                   float* __restrict__ out) {
    __shared__ float vsb[NPTS];
    int b = blockIdx.y, tid = threadIdx.x, lane = tid & 31, w = tid >> 5;
    const float* vrow = g_vs + b * NPTS;
    #pragma unroll
    for (int r = 0; r < NPTS/256; r++) vsb[r*256 + tid] = vrow[r*256 + tid] + BIASV;
    __syncthreads();

    int i = blockIdx.x * 8 + w;
    float ui = g_us[b*NREF + i];
    const unsigned short* Clor = g_Clo + ((size_t)b*NREF + i) * NPTS;
    const unsigned char*  Chir = g_Chi + ((size_t)b*NREF + i) * NPTS;
    const float* Xb = X + (size_t)b * NPTS * DIM;

    float acc0 = 0.f, acc1 = 0.f, acc2 = 0.f, acc3 = 0.f, den = 0.f;
    for (int jb = 0; jb < NPTS; jb += 32) {
        int j = jb + lane;
        unsigned lo = Clor[j];
        unsigned hi = Chir[j];
        float f = __uint_as_float(MAGIC | (hi << 16) | lo);
        float z = fmaf(-STEP, f, ui + vsb[j]);
        float wgt = 0.f;
        bool flag = z > -40.f;
        if (flag) wgt = __expf(z);
        unsigned act = __ballot_sync(FULLM, flag);
        while (act) {
            int p = __ffs(act) - 1; act &= act - 1;
            float wj = __shfl_sync(FULLM, wgt, p);
            const float* xr = Xb + (size_t)(jb + p) * DIM;
            acc0 = fmaf(wj, xr[lane     ], acc0);
            acc1 = fmaf(wj, xr[lane + 32], acc1);
            acc2 = fmaf(wj, xr[lane + 64], acc2);
            acc3 = fmaf(wj, xr[lane + 96], acc3);
            den += wj;
        }
    }
    float inv = 1.f / (den + 1e-8f);
    float* orow = out + ((size_t)b*NREF + i) * DIM;
    orow[lane     ] = acc0 * inv - REF[i*DIM + lane     ];
    orow[lane + 32] = acc1 * inv - REF[i*DIM + lane + 32];
    orow[lane + 64] = acc2 * inv - REF[i*DIM + lane + 64];
    orow[lane + 96] = acc3 * inv - REF[i*DIM + lane + 96];
}

extern "C" void kernel_launch(void* const* d_in, const int* in_sizes, int n_in,
                              void* d_out, int out_size) {
    const float* a = (const float*)d_in[0];
    const float* c = (const float*)d_in[1];
    const float *X, *REF;
    if (in_sizes[0] == NREF * DIM) { REF = a; X = c; }
    else                           { X = a;  REF = c; }
    float* out = (float*)d_out;

    int warps = B_*NPTS + NREF;
    aux_kernel<<<(warps*32 + 255) / 256, 256>>>(X, REF);

    dim3 cg(NPTS/64, NREF/64, B_);
    c_kernel<<<cg, 256>>>(X, REF);

    sinkhorn_cluster<<<2 * B_, 1024>>>();

    bary_kernel<<<dim3(NREF/8, B_), 256>>>(X, REF, out);
}